// round 9
// baseline (speedup 1.0000x reference)
#include <cuda_runtime.h>
#include <cuda_bf16.h>

// Problem constants (fixed by the reference setup)
#define NMAX  500000
#define KINST 512
#define DFEAT 256
#define HID   64
#define OUTC  32
#define NSEG  (KINST + 1)
#define PAD   32            // one counter per 128B line
#define SPLIT 4             // chunks per instance in the reduce phase
#define MLPGRID 296         // 2 resident blocks per SM, all start at t=0

#define RANKBITS 21
#define RANKMASK ((1 << RANKBITS) - 1)

// Device-global scratch (no allocations allowed).
// __device__ globals are zero-initialized at module load; k_mlp's tail and
// k_hist's last block restore the zeroed state each call -> deterministic.
__device__ int    g_counts[NSEG * PAD];     // padded histogram (atomic target)
__device__ int    g_offsets[KINST];         // exclusive scan (foreground only)
__device__ float  g_csum[KINST * PAD];      // padded: row k holds 3 floats at k*PAD
__device__ int    g_rank[NMAX];             // packed (seg<<21)|rank, or -1 for bg
__device__ int    g_sorted[NMAX];           // fg point indices bucketed by segment
__device__ float4 g_partial[KINST * SPLIT * 64];  // per-chunk partial feature sums
__device__ int    g_done;                   // last-block detector for fused scan

// ---------------------------------------------------------------------------
// 1) histogram + packed rank + coord sums; LAST block performs the exclusive
//    scan over the 512 foreground counts (fused: saves a kernel launch).
__global__ void k_hist(const int* __restrict__ ids,
                       const float* __restrict__ coords, int n) {
    int i = blockIdx.x * blockDim.x + threadIdx.x;
    if (i < n) {
        int id = ids[i];
        if (id >= 0) {
            int r = atomicAdd(&g_counts[id * PAD], 1);
            g_rank[i] = (id << RANKBITS) | r;
            atomicAdd(&g_csum[id * PAD + 0], coords[i * 3 + 0]);
            atomicAdd(&g_csum[id * PAD + 1], coords[i * 3 + 1]);
            atomicAdd(&g_csum[id * PAD + 2], coords[i * 3 + 2]);
        } else {
            g_rank[i] = -1;             // background: dropped
        }
    }
    // last-block-done detection
    __threadfence();
    __shared__ int is_last;
    if (threadIdx.x == 0)
        is_last = (atomicAdd(&g_done, 1) == (int)gridDim.x - 1);
    __syncthreads();
    if (!is_last) return;

    // exclusive scan of 512 counts with 256 threads (pair + Hillis-Steele)
    int t = threadIdx.x;                // 0..255, owns segs 2t, 2t+1
    int c0 = __ldcg(&g_counts[(2 * t) * PAD]);
    int c1 = __ldcg(&g_counts[(2 * t + 1) * PAD]);
    __shared__ int ssum[256];
    int p = c0 + c1;
    ssum[t] = p;
    __syncthreads();
    #pragma unroll
    for (int s = 1; s < 256; s <<= 1) {
        int x = (t >= s) ? ssum[t - s] : 0;
        __syncthreads();
        ssum[t] += x;
        __syncthreads();
    }
    int e = ssum[t] - p;                // exclusive pair offset
    g_offsets[2 * t]     = e;
    g_offsets[2 * t + 1] = e + c0;
    if (t == 0) g_done = 0;             // reset for next call
}

// ---------------------------------------------------------------------------
// 2) bucket foreground point indices by segment — atomic-free
__global__ void k_scatter(int n) {
    int i = blockIdx.x * blockDim.x + threadIdx.x;
    if (i >= n) return;
    int packed = g_rank[i];
    if (packed < 0) return;             // background
    int seg = packed >> RANKBITS;
    int r   = packed & RANKMASK;
    g_sorted[g_offsets[seg] + r] = i;
}

// ---------------------------------------------------------------------------
// 3) partial segment sums of features (the 512 MB kernel). SPLIT blocks per
//    instance. occupancy 6 blocks/SM (regs capped at 42), unroll 4 keeps
//    4 independent LDG.128 in flight per thread. __ldcs: read-once stream.
__global__ void __launch_bounds__(256, 6)
k_partial(const float* __restrict__ feat) {
    int bid = blockIdx.x;
    int k = bid >> 2;                   // instance
    int s = bid & (SPLIT - 1);          // chunk within instance
    int t = threadIdx.x;                // 0..255
    int g = t >> 6;                     // 0..3  point-interleave group
    int f = t & 63;                     // 0..63 feature quad
    int base = g_offsets[k];
    int c    = g_counts[k * PAD];
    int jlo = (c * s) >> 2;
    int jhi = (c * (s + 1)) >> 2;

    __shared__ int    sidx[256];
    __shared__ float4 red[256];

    float4 acc = make_float4(0.f, 0.f, 0.f, 0.f);
    for (int j0 = jlo; j0 < jhi; j0 += 256) {
        int m = min(256, jhi - j0);
        __syncthreads();
        if (t < m) sidx[t] = g_sorted[base + j0 + t];
        __syncthreads();
        #pragma unroll 4
        for (int j = g; j < m; j += 4) {
            const float4* row = (const float4*)(feat + (size_t)sidx[j] * DFEAT);
            float4 v = __ldcs(&row[f]);
            acc.x += v.x; acc.y += v.y; acc.z += v.z; acc.w += v.w;
        }
    }
    red[t] = acc;
    __syncthreads();
    if (t < 64) {
        float4 a0 = red[t], a1 = red[t + 64], a2 = red[t + 128], a3 = red[t + 192];
        float4 r;
        r.x = a0.x + a1.x + a2.x + a3.x;
        r.y = a0.y + a1.y + a2.y + a3.y;
        r.z = a0.z + a1.z + a2.z + a3.z;
        r.w = a0.w + a1.w + a2.w + a3.w;
        g_partial[bid * 64 + t] = r;
    }
}

// ---------------------------------------------------------------------------
// 4) finalize + centroids + tiny MLP. PERSISTENT: 296 blocks (2/SM, all
//    resident at t=0) grid-stride over the 512 instances -> no wave
//    serialization of the per-instance latency chain, and W1/W2/W3 stay hot
//    in L1 after the first instance on each SM.
//    Tail of each iteration: re-zero that instance's padded scratch rows.
__global__ void __launch_bounds__(256)
k_mlp(const float* __restrict__ W1, const float* __restrict__ W2,
      const float* __restrict__ W3, const float* __restrict__ b3,
      float* __restrict__ out) {
    int t = threadIdx.x;                // 0..255
    int j = t & 63;                     // output index for layers 1-2
    int grp = t >> 6;                   // 0..3 reduction group

    __shared__ float emb[DFEAT];
    __shared__ float red[256];
    __shared__ float h1[HID];
    __shared__ float h2[HID];

    for (int k = blockIdx.x; k < KINST; k += MLPGRID) {
        int c = g_counts[k * PAD];
        float inv = 1.0f / (float)((c > 1) ? c : 1);

        // deterministic combine of SPLIT partial sums, then mean
        if (t < 64) {
            float4 r = make_float4(0.f, 0.f, 0.f, 0.f);
            #pragma unroll
            for (int s = 0; s < SPLIT; s++) {
                float4 p = g_partial[(k * SPLIT + s) * 64 + t];
                r.x += p.x; r.y += p.y; r.z += p.z; r.w += p.w;
            }
            r.x *= inv; r.y *= inv; r.z *= inv; r.w *= inv;
            ((float4*)(out + (size_t)k * DFEAT))[t] = r;     // embeddings
            ((float4*)emb)[t] = r;
        }
        if (t < 3) out[KINST * DFEAT + k * 3 + t] = g_csum[k * PAD + t] * inv;
        __syncthreads();

        // layer 1: 64 outputs x 4 groups of 64 i's
        float s1 = 0.0f;
        {
            int i0 = grp * 64;
            #pragma unroll 4
            for (int i = i0; i < i0 + 64; i++) s1 += emb[i] * W1[i * HID + j];
        }
        red[t] = s1;
        __syncthreads();
        if (t < 64) h1[t] = fmaxf(red[t] + red[t + 64] + red[t + 128] + red[t + 192], 0.0f);
        __syncthreads();

        // layer 2: 64 outputs x 4 groups of 16 i's
        float s2 = 0.0f;
        {
            int i0 = grp * 16;
            #pragma unroll
            for (int i = i0; i < i0 + 16; i++) s2 += h1[i] * W2[i * HID + j];
        }
        red[t] = s2;
        __syncthreads();
        if (t < 64) h2[t] = fmaxf(red[t] + red[t + 64] + red[t + 128] + red[t + 192], 0.0f);
        __syncthreads();

        // layer 3: 32 outputs x 8 groups of 8 i's
        {
            int j3 = t & 31;
            int g3 = t >> 5;
            int i0 = g3 * 8;
            float s3 = 0.0f;
            #pragma unroll
            for (int i = i0; i < i0 + 8; i++) s3 += h2[i] * W3[i * OUTC + j3];
            red[t] = s3;
        }
        __syncthreads();
        if (t < OUTC) {
            float s3 = b3[t];
            #pragma unroll
            for (int g3 = 0; g3 < 8; g3++) s3 += red[t + g3 * 32];
            out[KINST * DFEAT + KINST * 3 + k * OUTC + t] = s3;
        }

        // tail: restore zeroed scratch for the next call (after all reads)
        __syncthreads();
        if (t < PAD) {
            g_counts[k * PAD + t] = 0;
            g_csum[k * PAD + t] = 0.0f;
            if (k == 0) g_counts[KINST * PAD + t] = 0;   // dummy row stays clean
        }
        __syncthreads();
    }
}

// ---------------------------------------------------------------------------
extern "C" void kernel_launch(void* const* d_in, const int* in_sizes, int n_in,
                              void* d_out, int out_size) {
    const float* feat   = (const float*)d_in[0];
    const float* coords = (const float*)d_in[1];
    const int*   ids    = (const int*)d_in[2];

    // num_instances may appear as a 1-element scalar input between ids and W1
    int wi = 3;
    if (n_in > 3 && in_sizes[3] == 1) wi = 4;
    const float* W1 = (const float*)d_in[wi];
    const float* W2 = (const float*)d_in[wi + 1];
    const float* W3 = (const float*)d_in[wi + 2];
    const float* b3 = (const float*)d_in[wi + 3];

    int n = in_sizes[2];                 // number of points
    float* out = (float*)d_out;

    int nb = (n + 255) / 256;
    k_hist<<<nb, 256>>>(ids, coords, n);        // includes fused scan
    k_scatter<<<nb, 256>>>(n);
    k_partial<<<KINST * SPLIT, 256>>>(feat);
    k_mlp<<<MLPGRID, 256>>>(W1, W2, W3, b3, out); // persistent, fused re-zero
}

// round 10
// speedup vs baseline: 1.1691x; 1.1691x over previous
#include <cuda_runtime.h>
#include <cuda_bf16.h>

// Problem constants (fixed by the reference setup)
#define NMAX  500000
#define KINST 512
#define DFEAT 256
#define HID   64
#define OUTC  32
#define PAD   32            // one counter per 128B line
#define SPLIT 4             // chunks per instance in the reduce phase

#define RANKBITS 21
#define RANKMASK ((1 << RANKBITS) - 1)

// Device-global scratch (no allocations allowed).
// __device__ globals are zero-initialized at module load; k_mlp's tail and
// k_hist's last block restore the zeroed state each call -> deterministic.
__device__ int    g_counts[(KINST + 1) * PAD];  // padded histogram (atomic target)
__device__ int    g_offsets[KINST];         // exclusive scan (foreground only)
__device__ int    g_rank[NMAX];             // packed (seg<<21)|rank, or -1 for bg
__device__ int    g_sorted[NMAX];           // fg point indices bucketed by segment
__device__ float4 g_partial[KINST * SPLIT * 64];  // per-chunk partial feature sums
__device__ int    g_done;                   // last-block detector for fused scan

// ---------------------------------------------------------------------------
// 1) histogram + packed rank (ONE atomic per foreground point); LAST block
//    performs the exclusive scan over the 512 counts (fused).
__global__ void k_hist(const int* __restrict__ ids, int n) {
    int i = blockIdx.x * blockDim.x + threadIdx.x;
    if (i < n) {
        int id = ids[i];
        if (id >= 0) {
            int r = atomicAdd(&g_counts[id * PAD], 1);
            g_rank[i] = (id << RANKBITS) | r;
        } else {
            g_rank[i] = -1;             // background: dropped
        }
    }
    // last-block-done detection
    __threadfence();
    __shared__ int is_last;
    if (threadIdx.x == 0)
        is_last = (atomicAdd(&g_done, 1) == (int)gridDim.x - 1);
    __syncthreads();
    if (!is_last) return;

    // exclusive scan of 512 counts with 256 threads (pair + Hillis-Steele)
    int t = threadIdx.x;                // 0..255, owns segs 2t, 2t+1
    int c0 = __ldcg(&g_counts[(2 * t) * PAD]);
    int c1 = __ldcg(&g_counts[(2 * t + 1) * PAD]);
    __shared__ int ssum[256];
    int p = c0 + c1;
    ssum[t] = p;
    __syncthreads();
    #pragma unroll
    for (int s = 1; s < 256; s <<= 1) {
        int x = (t >= s) ? ssum[t - s] : 0;
        __syncthreads();
        ssum[t] += x;
        __syncthreads();
    }
    int e = ssum[t] - p;                // exclusive pair offset
    g_offsets[2 * t]     = e;
    g_offsets[2 * t + 1] = e + c0;
    if (t == 0) g_done = 0;             // reset for next call
}

// ---------------------------------------------------------------------------
// 2) bucket foreground point indices by segment — atomic-free
__global__ void k_scatter(int n) {
    int i = blockIdx.x * blockDim.x + threadIdx.x;
    if (i >= n) return;
    int packed = g_rank[i];
    if (packed < 0) return;             // background
    int seg = packed >> RANKBITS;
    int r   = packed & RANKMASK;
    g_sorted[g_offsets[seg] + r] = i;
}

// ---------------------------------------------------------------------------
// 3) partial segment sums of features (the 512 MB kernel). SPLIT blocks per
//    instance. occupancy 6 blocks/SM (regs capped at 42), unroll 4 keeps
//    4 independent LDG.128 in flight per thread. __ldcs: read-once stream.
__global__ void __launch_bounds__(256, 6)
k_partial(const float* __restrict__ feat) {
    int bid = blockIdx.x;
    int k = bid >> 2;                   // instance
    int s = bid & (SPLIT - 1);          // chunk within instance
    int t = threadIdx.x;                // 0..255
    int g = t >> 6;                     // 0..3  point-interleave group
    int f = t & 63;                     // 0..63 feature quad
    int base = g_offsets[k];
    int c    = g_counts[k * PAD];
    int jlo = (c * s) >> 2;
    int jhi = (c * (s + 1)) >> 2;

    __shared__ int    sidx[256];
    __shared__ float4 red[256];

    float4 acc = make_float4(0.f, 0.f, 0.f, 0.f);
    for (int j0 = jlo; j0 < jhi; j0 += 256) {
        int m = min(256, jhi - j0);
        __syncthreads();
        if (t < m) sidx[t] = g_sorted[base + j0 + t];
        __syncthreads();
        #pragma unroll 4
        for (int j = g; j < m; j += 4) {
            const float4* row = (const float4*)(feat + (size_t)sidx[j] * DFEAT);
            float4 v = __ldcs(&row[f]);
            acc.x += v.x; acc.y += v.y; acc.z += v.z; acc.w += v.w;
        }
    }
    red[t] = acc;
    __syncthreads();
    if (t < 64) {
        float4 a0 = red[t], a1 = red[t + 64], a2 = red[t + 128], a3 = red[t + 192];
        float4 r;
        r.x = a0.x + a1.x + a2.x + a3.x;
        r.y = a0.y + a1.y + a2.y + a3.y;
        r.z = a0.z + a1.z + a2.z + a3.z;
        r.w = a0.w + a1.w + a2.w + a3.w;
        g_partial[bid * 64 + t] = r;
    }
}

// ---------------------------------------------------------------------------
// 4) finalize + CENTROID GATHER (replaces hist csum atomics) + tiny MLP.
//    One block per instance (512 blocks — R8-verified shape).
//    Tail: re-zero this instance's count for the next call.
__global__ void __launch_bounds__(256)
k_mlp(const float* __restrict__ coords,
      const float* __restrict__ W1, const float* __restrict__ W2,
      const float* __restrict__ W3, const float* __restrict__ b3,
      float* __restrict__ out) {
    int k = blockIdx.x;
    int t = threadIdx.x;                // 0..255
    int j = t & 63;                     // output index for layers 1-2
    int grp = t >> 6;                   // 0..3 reduction group

    __shared__ float emb[DFEAT];
    __shared__ float red[256];
    __shared__ float cred[3][256];
    __shared__ float h1[HID];
    __shared__ float h2[HID];

    int base = g_offsets[k];
    int c = g_counts[k * PAD];
    float inv = 1.0f / (float)((c > 1) ? c : 1);

    // centroid: gather coords via sorted indices (deterministic assignment)
    {
        float cx = 0.f, cy = 0.f, cz = 0.f;
        for (int i = t; i < c; i += 256) {
            int idx = g_sorted[base + i];
            cx += coords[idx * 3 + 0];
            cy += coords[idx * 3 + 1];
            cz += coords[idx * 3 + 2];
        }
        cred[0][t] = cx; cred[1][t] = cy; cred[2][t] = cz;
    }

    // combine SPLIT partial sums, then mean (runs while centroid data lands)
    if (t < 64) {
        float4 r = make_float4(0.f, 0.f, 0.f, 0.f);
        #pragma unroll
        for (int s = 0; s < SPLIT; s++) {
            float4 p = g_partial[(k * SPLIT + s) * 64 + t];
            r.x += p.x; r.y += p.y; r.z += p.z; r.w += p.w;
        }
        r.x *= inv; r.y *= inv; r.z *= inv; r.w *= inv;
        ((float4*)(out + (size_t)k * DFEAT))[t] = r;     // embeddings
        ((float4*)emb)[t] = r;
    }
    __syncthreads();

    // tree-reduce centroid partials
    #pragma unroll
    for (int s = 128; s > 0; s >>= 1) {
        if (t < s) {
            cred[0][t] += cred[0][t + s];
            cred[1][t] += cred[1][t + s];
            cred[2][t] += cred[2][t + s];
        }
        __syncthreads();
    }
    if (t < 3) out[KINST * DFEAT + k * 3 + t] = cred[t][0] * inv;

    // layer 1: 64 outputs x 4 groups of 64 i's
    float s1 = 0.0f;
    {
        int i0 = grp * 64;
        #pragma unroll 4
        for (int i = i0; i < i0 + 64; i++) s1 += emb[i] * W1[i * HID + j];
    }
    red[t] = s1;
    __syncthreads();
    if (t < 64) h1[t] = fmaxf(red[t] + red[t + 64] + red[t + 128] + red[t + 192], 0.0f);
    __syncthreads();

    // layer 2: 64 outputs x 4 groups of 16 i's
    float s2 = 0.0f;
    {
        int i0 = grp * 16;
        #pragma unroll
        for (int i = i0; i < i0 + 16; i++) s2 += h1[i] * W2[i * HID + j];
    }
    red[t] = s2;
    __syncthreads();
    if (t < 64) h2[t] = fmaxf(red[t] + red[t + 64] + red[t + 128] + red[t + 192], 0.0f);
    __syncthreads();

    // layer 3: 32 outputs x 8 groups of 8 i's
    {
        int j3 = t & 31;
        int g3 = t >> 5;
        int i0 = g3 * 8;
        float s3 = 0.0f;
        #pragma unroll
        for (int i = i0; i < i0 + 8; i++) s3 += h2[i] * W3[i * OUTC + j3];
        red[t] = s3;
    }
    __syncthreads();
    if (t < OUTC) {
        float s3 = b3[t];
        #pragma unroll
        for (int g3 = 0; g3 < 8; g3++) s3 += red[t + g3 * 32];
        out[KINST * DFEAT + KINST * 3 + k * OUTC + t] = s3;
    }

    // tail: restore zeroed counts for the next call (after all reads above)
    if (t == 0) g_counts[k * PAD] = 0;
}

// ---------------------------------------------------------------------------
extern "C" void kernel_launch(void* const* d_in, const int* in_sizes, int n_in,
                              void* d_out, int out_size) {
    const float* feat   = (const float*)d_in[0];
    const float* coords = (const float*)d_in[1];
    const int*   ids    = (const int*)d_in[2];

    // num_instances may appear as a 1-element scalar input between ids and W1
    int wi = 3;
    if (n_in > 3 && in_sizes[3] == 1) wi = 4;
    const float* W1 = (const float*)d_in[wi];
    const float* W2 = (const float*)d_in[wi + 1];
    const float* W3 = (const float*)d_in[wi + 2];
    const float* b3 = (const float*)d_in[wi + 3];

    int n = in_sizes[2];                 // number of points
    float* out = (float*)d_out;

    int nb = (n + 255) / 256;
    k_hist<<<nb, 256>>>(ids, n);                 // includes fused scan
    k_scatter<<<nb, 256>>>(n);
    k_partial<<<KINST * SPLIT, 256>>>(feat);
    k_mlp<<<KINST, 256>>>(coords, W1, W2, W3, b3, out); // centroids + MLP + re-zero
}